// round 7
// baseline (speedup 1.0000x reference)
#include <cuda_runtime.h>
#include <cstdint>

// ================= problem constants =================
#define NB   1024
#define IIC  128
#define MGLOB (NB*784)            // 802816 flattened output rows
#define MT    256                 // m per tile
#define NTILES (MGLOB/MT)         // 3136 exact
#define GRID_MAIN 152

// ================= scratch =================
// g_R[(n*28+h')][idx 0..31][l 0..31]  (tf32-rounded floats, 128B rows)
__device__ float g_R[(size_t)NB*28*32*32];   // 117 MB

// ================= smem layout =================
#define WS_BYTES   (36*8*32*16)                 // 147456 (S=36, mt=8, lane=32, uint4)
#define ACT_BYTES  32768                        // 4s * 32nt * 2reg * 32lane * 8B
#define ACT0_OFF   WS_BYTES                     // 147456
#define ACT1_OFF   (ACT0_OFF + ACT_BYTES)       // 180224
#define SM_TOTAL   (ACT1_OFF + ACT_BYTES)       // 212992

__device__ __forceinline__ uint32_t f2tf32(float v) {
    uint32_t o; asm("cvt.rna.tf32.f32 %0, %1;" : "=r"(o) : "f"(v)); return o;
}

__device__ __forceinline__ void mma_tf32(float4& d, const uint4& a, const uint2& b) {
    asm volatile(
        "mma.sync.aligned.m16n8k8.row.col.f32.tf32.tf32.f32 "
        "{%0,%1,%2,%3}, {%4,%5,%6,%7}, {%8,%9}, {%0,%1,%2,%3};"
        : "+f"(d.x), "+f"(d.y), "+f"(d.z), "+f"(d.w)
        : "r"(a.x), "r"(a.y), "r"(a.z), "r"(a.w), "r"(b.x), "r"(b.y));
}

__device__ __forceinline__ void cpasync16(uint32_t dst, const float* src, uint32_t nbytes) {
    asm volatile("cp.async.cg.shared.global [%0], [%1], 16, %2;"
                 :: "r"(dst), "l"(src), "r"(nbytes) : "memory");
}
#define CP_COMMIT() asm volatile("cp.async.commit_group;" ::: "memory")
#define CP_WAIT0()  asm volatile("cp.async.wait_group 0;" ::: "memory")

// ================= prep kernel: build g_R (validated R4-R6) =================
__global__ __launch_bounds__(128) void prep_kernel(const float* __restrict__ x) {
    __shared__ float xs[64 * 29];
    const int p = blockIdx.x;            // n*28 + h'
    const int n = p / 28, h = p - n * 28;
    const int tid = threadIdx.x;

    for (int e = tid; e < 64 * 28; e += 128) {
        const int c = e / 28, u = e - c * 28;
        xs[c * 29 + u] = x[(((size_t)n * 64 + c) * 28 + h) * 28 + u];
    }
    __syncthreads();

    float* Rout = g_R + (size_t)p * (32 * 32);
    const int l = tid & 31;
    const int q0 = tid >> 5;
    #pragma unroll
    for (int qq = 0; qq < 8; ++qq) {
        const int q = qq * 4 + q0;
        float v;
        if (q < 28) {
            int u1 = q - 1; if (u1 < 0) u1 += 28;
            int u2 = q - 2; if (u2 < 0) u2 += 28;
            v = xs[l * 29 + u1] + xs[(32 + l) * 29 + u2];
        } else if (q == 28) v = xs[(32 + l) * 29 + 25];   // k=0, w=0
        else if (q == 29)   v = xs[l * 29 + 27];          // k=0, w=1
        else if (q == 30)   v = xs[l * 29 + 0];           // k=2, w=0
        else                v = xs[(32 + l) * 29 + 26];   // k=2, w=27
        Rout[q * 32 + l] = __uint_as_float(f2tf32(v));
    }
}

// fragment-ready act addressing (same as R6): value (m = nt*8+mrel, l = slot*4+pos)
// float offset = ((s*32+nt)*2+reg)*32 + ((mrel^slot)<<2) + pos,  slot = s*2+reg
__device__ __forceinline__ int frag_off(int s, int nt, int reg, int mrel, int pos) {
    const int slot = s * 2 + reg;
    return (((s * 32 + nt) * 2 + reg) << 5) + ((mrel ^ slot) << 2) + pos;
}

// ================= main kernel =================
__global__ __launch_bounds__(512, 1) void main_kernel(const float* __restrict__ Wg,
                                                      float* __restrict__ out) {
    extern __shared__ char smem[];
    float* ws = reinterpret_cast<float*>(smem);
    const uint4* ws4 = reinterpret_cast<const uint4*>(smem);
    const float* act0 = reinterpret_cast<float*>(smem + ACT0_OFF);
    const float* act1 = reinterpret_cast<float*>(smem + ACT1_OFF);
    const uint32_t smem_u32 = (uint32_t)__cvta_generic_to_shared(smem);

    const int tid  = threadIdx.x;
    const int lane = tid & 31;
    const int w    = tid >> 5;
    const int warp_i = w & 1;       // 64i half
    const int warp_m = w >> 1;      // 8 m-octants of 32m

    // ---- weights (full 128i) -> fragment-ready smem, once ----
    for (int e = tid; e < 288 * 128; e += 512) {
        const int kko = e >> 7;               // l*9 + c
        const int i   = e & 127;
        const float v = Wg[e];
        const int l = kko / 9;
        const int c = kko - l * 9;
        const int kp = c * 32 + l;
        const int S = kp >> 3, kk8 = kp & 7;
        const int mt = i >> 4, r = i & 15;
        const int t = ((r & 7) << 2) + (kk8 & 3);
        const int reg = (r >> 3) + ((kk8 >> 2) << 1);
        ws[(((S << 3) + mt) * 32 + t) * 4 + reg] = __uint_as_float(f2tf32(v));
    }
    // first tile's post-stage0 __syncthreads orders these before any MMA

    // ---- per-thread staging identity: 4 m-rows, one 16B slot each ----
    const int srow4 = lane >> 3;      // row within group of 4
    const int slot  = lane & 7;       // 16B slot (l = slot*4 .. +3)
    const int s_s   = slot >> 1;
    const int s_reg = slot & 1;

    uint32_t dstq[4];                 // smem byte addr within an act buffer
    #pragma unroll
    for (int q = 0; q < 4; ++q) {
        const int m_loc = (w << 4) + (q << 2) + srow4;
        dstq[q] = smem_u32 + ACT0_OFF
                + (uint32_t)(frag_off(s_s, m_loc >> 3, s_reg, m_loc & 7, 0) << 2);
    }

    for (int g = blockIdx.x; g < NTILES; g += gridDim.x) {
        const int mbase = g * MT;

        // per-tile row metadata (registers only)
        int hq[4], rbq[4], ik0q[4], ik1q[4], ik2q[4];
        #pragma unroll
        for (int q = 0; q < 4; ++q) {
            const int m_loc = (w << 4) + (q << 2) + srow4;
            const int mg = mbase + m_loc;
            const int n  = mg / 784;
            const int r  = mg - n * 784;
            const int h  = r / 28;
            const int wp = r - h * 28;
            hq[q]  = h;
            rbq[q] = n * 28;
            ik0q[q] = (wp == 0) ? 28 : (wp == 1) ? 29 : (wp - 1);
            ik1q[q] = wp;
            ik2q[q] = (wp == 0) ? 30 : (wp == 27) ? 31 : (wp + 1);
        }

        // ---- stage chunk 0 (j=0,k=0) ----
        #pragma unroll
        for (int q = 0; q < 4; ++q) {
            const int hp = hq[q] - 1;
            const bool v = ((unsigned)hp < 28u);
            const int off = v ? ((((rbq[q] + hp) << 5) + ik0q[q]) << 5) : 0;
            cpasync16(dstq[q], g_R + off + (slot << 2), v ? 16u : 0u);
        }
        CP_COMMIT();
        CP_WAIT0();
        __syncthreads();

        float4 acc[4][4];
        #pragma unroll
        for (int a = 0; a < 4; ++a)
            #pragma unroll
            for (int b = 0; b < 4; ++b)
                acc[a][b] = make_float4(0.f, 0.f, 0.f, 0.f);

        // ---- 9 chunks: cp.async(c+1) -> MMA(c) -> wait -> sync ----
        #pragma unroll 1
        for (int c = 0; c < 9; ++c) {
            if (c < 8) {
                const int cn = c + 1;
                const int j = (cn * 11) >> 5;     // cn/3
                const int k = cn - j * 3;
                const uint32_t bsel = (cn & 1) ? (ACT1_OFF - ACT0_OFF) : 0u;
                #pragma unroll
                for (int q = 0; q < 4; ++q) {
                    const int hp = hq[q] + j - 1;
                    const bool v = ((unsigned)hp < 28u);
                    const int ik = (k == 0) ? ik0q[q] : (k == 1) ? ik1q[q] : ik2q[q];
                    const int off = v ? ((((rbq[q] + hp) << 5) + ik) << 5) : 0;
                    cpasync16(dstq[q] + bsel, g_R + off + (slot << 2), v ? 16u : 0u);
                }
                CP_COMMIT();
            }

            const float* bufc = (c & 1) ? act1 : act0;
            const int mrel = lane >> 2, pos = lane & 3;
            #pragma unroll
            for (int s = 0; s < 4; ++s) {
                uint4 afr[4];
                #pragma unroll
                for (int mtl = 0; mtl < 4; ++mtl)
                    afr[mtl] = ws4[(((c * 4 + s) << 3) + warp_i * 4 + mtl) * 32 + lane];
                uint2 bfr[4];
                #pragma unroll
                for (int ntl = 0; ntl < 4; ++ntl) {
                    const int nt = warp_m * 4 + ntl;
                    bfr[ntl].x = __float_as_uint(bufc[frag_off(s, nt, 0, mrel, pos)]);
                    bfr[ntl].y = __float_as_uint(bufc[frag_off(s, nt, 1, mrel, pos)]);
                }
                #pragma unroll
                for (int mtl = 0; mtl < 4; ++mtl)
                    #pragma unroll
                    for (int ntl = 0; ntl < 4; ++ntl)
                        mma_tf32(acc[mtl][ntl], afr[mtl], bfr[ntl]);
            }

            if (c < 8) CP_WAIT0();
            __syncthreads();
        }

        // ---- epilogue: coalesced float2 stores ----
        #pragma unroll
        for (int mtl = 0; mtl < 4; ++mtl) {
            const int i0 = warp_i * 64 + mtl * 16 + (lane >> 2);
            #pragma unroll
            for (int ntl = 0; ntl < 4; ++ntl) {
                const int mgo = mbase + warp_m * 32 + ntl * 8 + ((lane & 3) << 1);
                const int n = mgo / 784;
                const int r = mgo - n * 784;     // float2 never straddles n (mgo even)
                const float4 v = acc[mtl][ntl];
                float* ob = out + (size_t)n * (IIC * 784) + r;
                *reinterpret_cast<float2*>(ob + (size_t)i0 * 784)       = make_float2(v.x, v.y);
                *reinterpret_cast<float2*>(ob + (size_t)(i0 + 8) * 784) = make_float2(v.z, v.w);
            }
        }
        // no extra sync: all warps passed the c=8 barrier (MMA reads done);
        // next tile's cp.async writes race only with nothing (epilogue is reg/global).
    }
}

// ================= launch =================
extern "C" void kernel_launch(void* const* d_in, const int* in_sizes, int n_in,
                              void* d_out, int out_size) {
    const float* x  = (const float*)d_in[0];   // (1024,64,28,28)
    const float* Wg = (const float*)d_in[1];   // (32,3,3,128)
    float* out = (float*)d_out;                // (1024,128,28,28)

    prep_kernel<<<NB * 28, 128>>>(x);

    cudaFuncSetAttribute(main_kernel, cudaFuncAttributeMaxDynamicSharedMemorySize, SM_TOTAL);
    main_kernel<<<GRID_MAIN, 512, SM_TOTAL>>>(Wg, out);
}

// round 8
// speedup vs baseline: 1.3247x; 1.3247x over previous
#include <cuda_runtime.h>
#include <cstdint>

// ================= problem constants =================
#define NB   1024
#define IIC  128
#define MGLOB (NB*784)            // 802816 flattened output rows
#define MT    256                 // m per tile
#define NTILES (MGLOB/MT)         // 3136 exact
#define GRID_MAIN 152

// ================= scratch =================
// g_R[(n*28+h')][idx 0..31][l 0..31]  (tf32-rounded floats, 128B rows)
__device__ float g_R[(size_t)NB*28*32*32];   // 117 MB

// ================= smem layout =================
#define WS_BYTES   (36*8*32*16)                 // 147456 (S=36, mt=8, lane=32, uint4)
#define ACT_FLOATS 8192                         // 32KB per buffer
#define ACT0_OFF   WS_BYTES
#define ACT1_OFF   (ACT0_OFF + ACT_FLOATS*4)
#define SM_TOTAL   (ACT1_OFF + ACT_FLOATS*4)    // 212992

__device__ __forceinline__ uint32_t f2tf32(float v) {
    uint32_t o; asm("cvt.rna.tf32.f32 %0, %1;" : "=r"(o) : "f"(v)); return o;
}

__device__ __forceinline__ void mma_tf32(float4& d, const uint4& a, const uint2& b) {
    asm volatile(
        "mma.sync.aligned.m16n8k8.row.col.f32.tf32.tf32.f32 "
        "{%0,%1,%2,%3}, {%4,%5,%6,%7}, {%8,%9}, {%0,%1,%2,%3};"
        : "+f"(d.x), "+f"(d.y), "+f"(d.z), "+f"(d.w)
        : "r"(a.x), "r"(a.y), "r"(a.z), "r"(a.w), "r"(b.x), "r"(b.y));
}

// pair-local named barrier: warps {2p, 2p+1}, 64 threads, id p+1
#define PAIRBAR(p) asm volatile("bar.sync %0, 64;" :: "r"((p) + 1) : "memory")

// ================= prep kernel: build g_R (validated R4-R7) =================
__global__ __launch_bounds__(128) void prep_kernel(const float* __restrict__ x) {
    __shared__ float xs[64 * 29];
    const int p = blockIdx.x;            // n*28 + h'
    const int n = p / 28, h = p - n * 28;
    const int tid = threadIdx.x;

    for (int e = tid; e < 64 * 28; e += 128) {
        const int c = e / 28, u = e - c * 28;
        xs[c * 29 + u] = x[(((size_t)n * 64 + c) * 28 + h) * 28 + u];
    }
    __syncthreads();

    float* Rout = g_R + (size_t)p * (32 * 32);
    const int l = tid & 31;
    const int q0 = tid >> 5;
    #pragma unroll
    for (int qq = 0; qq < 8; ++qq) {
        const int q = qq * 4 + q0;
        float v;
        if (q < 28) {
            int u1 = q - 1; if (u1 < 0) u1 += 28;
            int u2 = q - 2; if (u2 < 0) u2 += 28;
            v = xs[l * 29 + u1] + xs[(32 + l) * 29 + u2];
        } else if (q == 28) v = xs[(32 + l) * 29 + 25];   // k=0, w=0
        else if (q == 29)   v = xs[l * 29 + 27];          // k=0, w=1
        else if (q == 30)   v = xs[l * 29 + 0];           // k=2, w=0
        else                v = xs[(32 + l) * 29 + 26];   // k=2, w=27
        Rout[q * 32 + l] = __uint_as_float(f2tf32(v));
    }
}

// fragment-ready act addressing (validated R6): value (m = nt*8+mrel, l = slot*4+pos)
// float offset = ((s*32+nt)*2+reg)*32 + ((mrel^slot)<<2) + pos,  slot = s*2+reg
__device__ __forceinline__ int frag_off(int s, int nt, int reg, int mrel, int pos) {
    const int slot = s * 2 + reg;
    return (((s * 32 + nt) * 2 + reg) << 5) + ((mrel ^ slot) << 2) + pos;
}

// ================= main kernel =================
__global__ __launch_bounds__(512, 1) void main_kernel(const float* __restrict__ Wg,
                                                      float* __restrict__ out) {
    extern __shared__ char smem[];
    float* ws = reinterpret_cast<float*>(smem);
    const uint4* ws4 = reinterpret_cast<const uint4*>(smem);
    float* actb[2] = { reinterpret_cast<float*>(smem + ACT0_OFF),
                       reinterpret_cast<float*>(smem + ACT1_OFF) };

    const int tid  = threadIdx.x;
    const int lane = tid & 31;
    const int w    = tid >> 5;
    const int warp_i = w & 1;       // 64i half
    const int warp_m = w >> 1;      // pair id p: m-octant of 32m

    // ---- weights (full 128i) -> fragment-ready smem, once ----
    for (int e = tid; e < 288 * 128; e += 512) {
        const int kko = e >> 7;               // l*9 + c
        const int i   = e & 127;
        const float v = Wg[e];
        const int l = kko / 9;
        const int c = kko - l * 9;
        const int kp = c * 32 + l;
        const int S = kp >> 3, kk8 = kp & 7;
        const int mt = i >> 4, r = i & 15;
        const int t = ((r & 7) << 2) + (kk8 & 3);
        const int reg = (r >> 3) + ((kk8 >> 2) << 1);
        ws[(((S << 3) + mt) * 32 + t) * 4 + reg] = __uint_as_float(f2tf32(v));
    }
    __syncthreads();   // only full-CTA barrier: weights visible to all

    // ---- per-thread staging identity: 4 m-rows within the pair's 32-row span ----
    const int srow4 = lane >> 3;      // row within group of 4
    const int slot  = lane & 7;       // 16B slot (l = slot*4 .. +3)
    const int s_s   = slot >> 1;
    const int s_reg = slot & 1;

    int dstf[4];                      // float index into an act buffer
    #pragma unroll
    for (int q = 0; q < 4; ++q) {
        const int m_loc = warp_m * 32 + warp_i * 16 + q * 4 + srow4;
        dstf[q] = frag_off(s_s, m_loc >> 3, s_reg, m_loc & 7, 0);
    }

    for (int g = blockIdx.x; g < NTILES; g += gridDim.x) {
        const int mbase = g * MT;

        // per-row metadata in registers (packed ik)
        int hq[4], baseq[4], ikp[4];
        #pragma unroll
        for (int q = 0; q < 4; ++q) {
            const int m_loc = warp_m * 32 + warp_i * 16 + q * 4 + srow4;
            const int mg = mbase + m_loc;
            const int n  = mg / 784;
            const int r  = mg - n * 784;
            const int h  = r / 28;
            const int wp = r - h * 28;
            hq[q]    = h;
            baseq[q] = (n * 28 + h) << 10;    // ((n*28+h)*32)*32
            const int ik0 = (wp == 0) ? 28 : (wp == 1) ? 29 : (wp - 1);
            const int ik2 = (wp == 0) ? 30 : (wp == 27) ? 31 : (wp + 1);
            ikp[q] = ik0 | (wp << 5) | (ik2 << 10);
        }

        // ---- prologue: LDG(0) -> STS(0) -> LDG(1) -> pairbar ----
        float4 sv[4];
        #pragma unroll
        for (int q = 0; q < 4; ++q) {                     // chunk 0: j=0, k=0
            const int hp = hq[q] - 1;
            const bool v = ((unsigned)hp < 28u);
            const int off = baseq[q] - 1024 + ((ikp[q] & 31) << 5);
            sv[q] = make_float4(0.f, 0.f, 0.f, 0.f);
            if (v) sv[q] = *reinterpret_cast<const float4*>(g_R + off + (slot << 2));
        }
        #pragma unroll
        for (int q = 0; q < 4; ++q)
            *reinterpret_cast<float4*>(actb[0] + dstf[q]) = sv[q];
        #pragma unroll
        for (int q = 0; q < 4; ++q) {                     // chunk 1: j=0, k=1
            const int hp = hq[q] - 1;
            const bool v = ((unsigned)hp < 28u);
            const int off = baseq[q] - 1024 + (((ikp[q] >> 5) & 31) << 5);
            sv[q] = make_float4(0.f, 0.f, 0.f, 0.f);
            if (v) sv[q] = *reinterpret_cast<const float4*>(g_R + off + (slot << 2));
        }
        PAIRBAR(warp_m);

        float4 acc[4][4];
        #pragma unroll
        for (int a = 0; a < 4; ++a)
            #pragma unroll
            for (int b = 0; b < 4; ++b)
                acc[a][b] = make_float4(0.f, 0.f, 0.f, 0.f);

        // ---- 9 chunks: STS(c+1) -> LDG(c+2) -> MMA(c) -> pairbar ----
        #pragma unroll 1
        for (int c = 0; c < 9; ++c) {
            if (c < 8) {
                float* bufn = actb[(c + 1) & 1];
                #pragma unroll
                for (int q = 0; q < 4; ++q)
                    *reinterpret_cast<float4*>(bufn + dstf[q]) = sv[q];
            }
            if (c < 7) {
                const int cn = c + 2;
                const int j = (cn * 11) >> 5;     // cn/3
                const int k = cn - j * 3;
                #pragma unroll
                for (int q = 0; q < 4; ++q) {
                    const int hp = hq[q] + j - 1;
                    const bool v = ((unsigned)hp < 28u);
                    const int ik = (ikp[q] >> (k * 5)) & 31;
                    const int off = baseq[q] + ((j - 1) << 10) + (ik << 5);
                    sv[q] = make_float4(0.f, 0.f, 0.f, 0.f);
                    if (v) sv[q] = *reinterpret_cast<const float4*>(g_R + off + (slot << 2));
                }
            }

            const float* bufc = actb[c & 1];
            const int mrel = lane >> 2, pos = lane & 3;
            #pragma unroll
            for (int s = 0; s < 4; ++s) {
                uint4 afr[4];
                #pragma unroll
                for (int mtl = 0; mtl < 4; ++mtl)
                    afr[mtl] = ws4[(((c * 4 + s) << 3) + warp_i * 4 + mtl) * 32 + lane];
                uint2 bfr[4];
                #pragma unroll
                for (int ntl = 0; ntl < 4; ++ntl) {
                    const int nt = warp_m * 4 + ntl;
                    bfr[ntl].x = __float_as_uint(bufc[frag_off(s, nt, 0, mrel, pos)]);
                    bfr[ntl].y = __float_as_uint(bufc[frag_off(s, nt, 1, mrel, pos)]);
                }
                #pragma unroll
                for (int mtl = 0; mtl < 4; ++mtl)
                    #pragma unroll
                    for (int ntl = 0; ntl < 4; ++ntl)
                        mma_tf32(acc[mtl][ntl], afr[mtl], bfr[ntl]);
            }

            PAIRBAR(warp_m);   // pair's STS(c+1) visible; pair's MMA(c) reads done
        }

        // ---- epilogue: coalesced float2 stores (registers/global only) ----
        #pragma unroll
        for (int mtl = 0; mtl < 4; ++mtl) {
            const int i0 = warp_i * 64 + mtl * 16 + (lane >> 2);
            #pragma unroll
            for (int ntl = 0; ntl < 4; ++ntl) {
                const int mgo = mbase + warp_m * 32 + ntl * 8 + ((lane & 3) << 1);
                const int n = mgo / 784;
                const int r = mgo - n * 784;     // float2 never straddles n (mgo even)
                const float4 v = acc[mtl][ntl];
                float* ob = out + (size_t)n * (IIC * 784) + r;
                *reinterpret_cast<float2*>(ob + (size_t)i0 * 784)       = make_float2(v.x, v.y);
                *reinterpret_cast<float2*>(ob + (size_t)(i0 + 8) * 784) = make_float2(v.z, v.w);
            }
        }
        // next tile's prologue STS(0) into actb[0] is pair-ordered by the c=8 PAIRBAR
        // (buf(0) readers are the pair's own MMAs of chunk 8, done before that barrier).
    }
}

// ================= launch =================
extern "C" void kernel_launch(void* const* d_in, const int* in_sizes, int n_in,
                              void* d_out, int out_size) {
    const float* x  = (const float*)d_in[0];   // (1024,64,28,28)
    const float* Wg = (const float*)d_in[1];   // (32,3,3,128)
    float* out = (float*)d_out;                // (1024,128,28,28)

    prep_kernel<<<NB * 28, 128>>>(x);

    cudaFuncSetAttribute(main_kernel, cudaFuncAttributeMaxDynamicSharedMemorySize, SM_TOTAL);
    main_kernel<<<GRID_MAIN, 512, SM_TOTAL>>>(Wg, out);
}

// round 9
// speedup vs baseline: 2.3358x; 1.7632x over previous
#include <cuda_runtime.h>
#include <cuda_fp16.h>
#include <cstdint>

// ================= problem constants =================
#define NB   1024
#define IIC  128
#define MGLOB (NB*784)            // 802816 flattened output rows
#define MT    128                 // m per tile
#define NTILES (MGLOB/MT)         // 6272 exact
#define GRID_MAIN 304
#define THREADS 256

// ================= scratch =================
// g_R[(n*28+h')][idx 0..31][l 0..31]  fp16, 64B rows
__device__ __half g_R[(size_t)NB*28*32*32];   // 58.7 MB

// ================= smem layout =================
// weights frag-ready: b32[t], t = ((S*8+mt)*32 + lane)*4 + reg, S=0..17
#define WS_B32   (18*8*32*4)                    // 18432 b32 = 73728 B
#define WS_BYTES (WS_B32*4)
// act buffer: b32 idx = ((rr*16+nt)<<5) + ((g^(rr<<1))<<2) + tig ; rr=s*2+reg
#define ACT_B32  2048                           // 8192 B per buffer
#define ACT0_OFF WS_BYTES                       // 73728
#define ACT1_OFF (ACT0_OFF + ACT_B32*4)         // 81920
#define SM_TOTAL (ACT1_OFF + ACT_B32*4)         // 90112

__device__ __forceinline__ void mma_f16(float4& d, const uint4& a, const uint2& b) {
    asm volatile(
        "mma.sync.aligned.m16n8k16.row.col.f32.f16.f16.f32 "
        "{%0,%1,%2,%3}, {%4,%5,%6,%7}, {%8,%9}, {%0,%1,%2,%3};"
        : "+f"(d.x), "+f"(d.y), "+f"(d.z), "+f"(d.w)
        : "r"(a.x), "r"(a.y), "r"(a.z), "r"(a.w), "r"(b.x), "r"(b.y));
}

// pair-local named barrier: warps {2p, 2p+1}, 64 threads, id p+1
#define PAIRBAR(p) asm volatile("bar.sync %0, 64;" :: "r"((p) + 1) : "memory")

// ================= prep kernel: build g_R (R4-validated math, fp16 out, f4 loads) ====
__global__ __launch_bounds__(128) void prep_kernel(const float* __restrict__ x) {
    __shared__ float xs[64 * 29];
    const int p = blockIdx.x;            // n*28 + h'
    const int n = p / 28, h = p - n * 28;
    const int tid = threadIdx.x;

    // coalesced float4 loads: 64 rows x 7 float4
    const float4* x4 = reinterpret_cast<const float4*>(x);
    #pragma unroll 4
    for (int e = tid; e < 448; e += 128) {
        const int c = e / 7, f = e - c * 7;
        const float4 v = x4[((size_t)(n * 64 + c) * 28 + h) * 7 + f];
        float* dst = &xs[c * 29 + f * 4];
        dst[0] = v.x; dst[1] = v.y; dst[2] = v.z; dst[3] = v.w;
    }
    __syncthreads();

    __half* Rout = g_R + (size_t)p * 1024;
    const int l = tid & 31;
    const int q0 = tid >> 5;
    #pragma unroll
    for (int qq = 0; qq < 8; ++qq) {
        const int q = qq * 4 + q0;
        float v;
        if (q < 28) {
            int u1 = q - 1; if (u1 < 0) u1 += 28;
            int u2 = q - 2; if (u2 < 0) u2 += 28;
            v = xs[l * 29 + u1] + xs[(32 + l) * 29 + u2];
        } else if (q == 28) v = xs[(32 + l) * 29 + 25];   // k=0, w=0
        else if (q == 29)   v = xs[l * 29 + 27];          // k=0, w=1
        else if (q == 30)   v = xs[l * 29 + 0];           // k=2, w=0
        else                v = xs[(32 + l) * 29 + 26];   // k=2, w=27
        Rout[q * 32 + l] = __float2half_rn(v);
    }
}

// ================= main kernel =================
__global__ __launch_bounds__(THREADS, 2) void main_kernel(const float* __restrict__ Wg,
                                                          float* __restrict__ out) {
    extern __shared__ char smem[];
    uint32_t* wsb = reinterpret_cast<uint32_t*>(smem);
    const uint4* ws4 = reinterpret_cast<const uint4*>(smem);
    uint32_t* actb[2] = { reinterpret_cast<uint32_t*>(smem + ACT0_OFF),
                          reinterpret_cast<uint32_t*>(smem + ACT1_OFF) };

    const int tid  = threadIdx.x;
    const int lane = tid & 31;
    const int w    = tid >> 5;
    const int warp_i = w & 1;       // 64i half
    const int warp_m = w >> 1;      // pair id p: 32m octant
    const int gq  = lane >> 2;      // fragment groupID
    const int tig = lane & 3;       // thread-in-group

    // ---- weights -> fp16 fragment-ready smem, once per CTA ----
    for (int t = tid; t < WS_B32; t += THREADS) {
        const int reg = t & 3;
        const int ln  = (t >> 2) & 31;
        const int mt  = (t >> 7) & 7;
        const int S   = t >> 10;                  // 0..17
        const int r   = (ln >> 2) + ((reg & 1) << 3);
        const int k16 = ((ln & 3) << 1) + ((reg >> 1) << 3);
        const int i   = (mt << 4) + r;
        const int kp  = (S << 4) + k16;           // even
        const int c   = kp >> 5, l = kp & 31;
        const float w0 = Wg[(l * 9 + c) * 128 + i];
        const float w1 = Wg[((l + 1) * 9 + c) * 128 + i];
        const __half2 hv = __floats2half2_rn(w0, w1);
        wsb[t] = *reinterpret_cast<const uint32_t*>(&hv);
    }
    __syncthreads();

    // rr-dependent swizzled lane offsets for B-frag loads
    int lofs[4];
    #pragma unroll
    for (int rr = 0; rr < 4; ++rr)
        lofs[rr] = ((gq ^ (rr << 1)) << 2) + tig;

    // ---- staging identity: 2 q-rows of 8, one 16B slot (8 l) each ----
    const int srow = lane >> 2;     // 0..7
    const int slot = lane & 3;      // rr
    int dstb[2];
    #pragma unroll
    for (int q = 0; q < 2; ++q) {
        const int m_loc = warp_m * 32 + warp_i * 16 + q * 8 + srow;
        dstb[q] = (((slot << 4) + (m_loc >> 3)) << 5)
                + (((m_loc & 7) ^ (slot << 1)) << 2);
    }

    for (int g = blockIdx.x; g < NTILES; g += gridDim.x) {
        const int mbase = g * MT;

        // per-row metadata (registers)
        int hq[2], baseq[2], ikp[2];
        #pragma unroll
        for (int q = 0; q < 2; ++q) {
            const int m_loc = warp_m * 32 + warp_i * 16 + q * 8 + srow;
            const int mg = mbase + m_loc;
            const int n  = mg / 784;
            const int r  = mg - n * 784;
            const int h  = r / 28;
            const int wp = r - h * 28;
            hq[q]    = h;
            baseq[q] = (n * 28 + h) << 10;        // halves
            const int ik0 = (wp == 0) ? 28 : (wp == 1) ? 29 : (wp - 1);
            const int ik2 = (wp == 0) ? 30 : (wp == 27) ? 31 : (wp + 1);
            ikp[q] = ik0 | (wp << 5) | (ik2 << 10);
        }

        // ---- prologue: LDG(0) -> STS(0) -> LDG(1) -> pairbar ----
        uint4 sv[2];
        #pragma unroll
        for (int q = 0; q < 2; ++q) {             // chunk 0: j=0,k=0
            const int hp = hq[q] - 1;
            const int off = baseq[q] - 1024 + ((ikp[q] & 31) << 5);
            sv[q] = make_uint4(0u, 0u, 0u, 0u);
            if ((unsigned)hp < 28u)
                sv[q] = *reinterpret_cast<const uint4*>(g_R + off + (slot << 3));
        }
        #pragma unroll
        for (int q = 0; q < 2; ++q)
            *reinterpret_cast<uint4*>(actb[0] + dstb[q]) = sv[q];
        #pragma unroll
        for (int q = 0; q < 2; ++q) {             // chunk 1: j=0,k=1
            const int hp = hq[q] - 1;
            const int off = baseq[q] - 1024 + (((ikp[q] >> 5) & 31) << 5);
            sv[q] = make_uint4(0u, 0u, 0u, 0u);
            if ((unsigned)hp < 28u)
                sv[q] = *reinterpret_cast<const uint4*>(g_R + off + (slot << 3));
        }
        PAIRBAR(warp_m);

        float4 acc[4][4];
        #pragma unroll
        for (int a = 0; a < 4; ++a)
            #pragma unroll
            for (int b = 0; b < 4; ++b)
                acc[a][b] = make_float4(0.f, 0.f, 0.f, 0.f);

        // ---- 9 chunks: STS(c+1) -> LDG(c+2) -> MMA(c) -> pairbar ----
        #pragma unroll 1
        for (int c = 0; c < 9; ++c) {
            if (c < 8) {
                uint32_t* bufn = actb[(c + 1) & 1];
                #pragma unroll
                for (int q = 0; q < 2; ++q)
                    *reinterpret_cast<uint4*>(bufn + dstb[q]) = sv[q];
            }
            if (c < 7) {
                const int cn = c + 2;
                const int j = (cn * 11) >> 5;     // cn/3
                const int k = cn - j * 3;
                #pragma unroll
                for (int q = 0; q < 2; ++q) {
                    const int hp = hq[q] + j - 1;
                    const int ik = (ikp[q] >> (k * 5)) & 31;
                    const int off = baseq[q] + ((j - 1) << 10) + (ik << 5);
                    sv[q] = make_uint4(0u, 0u, 0u, 0u);
                    if ((unsigned)hp < 28u)
                        sv[q] = *reinterpret_cast<const uint4*>(g_R + off + (slot << 3));
                }
            }

            const uint32_t* bufc = actb[c & 1];
            #pragma unroll
            for (int s = 0; s < 2; ++s) {
                const int S = c * 2 + s;
                uint4 afr[4];
                #pragma unroll
                for (int mtl = 0; mtl < 4; ++mtl)
                    afr[mtl] = ws4[((S << 3) + warp_i * 4 + mtl) * 32 + lane];
                uint2 bfr[4];
                const int rr0 = s * 2, rr1 = s * 2 + 1;
                #pragma unroll
                for (int ntl = 0; ntl < 4; ++ntl) {
                    const int nt = warp_m * 4 + ntl;
                    bfr[ntl].x = bufc[(((rr0 << 4) + nt) << 5) + lofs[rr0]];
                    bfr[ntl].y = bufc[(((rr1 << 4) + nt) << 5) + lofs[rr1]];
                }
                #pragma unroll
                for (int mtl = 0; mtl < 4; ++mtl)
                    #pragma unroll
                    for (int ntl = 0; ntl < 4; ++ntl)
                        mma_f16(acc[mtl][ntl], afr[mtl], bfr[ntl]);
            }

            PAIRBAR(warp_m);
        }

        // ---- epilogue: coalesced float2 stores ----
        #pragma unroll
        for (int mtl = 0; mtl < 4; ++mtl) {
            const int i0 = warp_i * 64 + mtl * 16 + gq;
            #pragma unroll
            for (int ntl = 0; ntl < 4; ++ntl) {
                const int mgo = mbase + warp_m * 32 + ntl * 8 + (tig << 1);
                const int n = mgo / 784;
                const int r = mgo - n * 784;     // float2 never straddles n (mgo even)
                const float4 v = acc[mtl][ntl];
                float* ob = out + (size_t)n * (IIC * 784) + r;
                *reinterpret_cast<float2*>(ob + (size_t)i0 * 784)       = make_float2(v.x, v.y);
                *reinterpret_cast<float2*>(ob + (size_t)(i0 + 8) * 784) = make_float2(v.z, v.w);
            }
        }
        // next tile's prologue STS(0) into actb[0] is pair-ordered by the c=8 PAIRBAR
    }
}

// ================= launch =================
extern "C" void kernel_launch(void* const* d_in, const int* in_sizes, int n_in,
                              void* d_out, int out_size) {
    const float* x  = (const float*)d_in[0];   // (1024,64,28,28)
    const float* Wg = (const float*)d_in[1];   // (32,3,3,128)
    float* out = (float*)d_out;                // (1024,128,28,28)

    prep_kernel<<<NB * 28, 128>>>(x);

    cudaFuncSetAttribute(main_kernel, cudaFuncAttributeMaxDynamicSharedMemorySize, SM_TOTAL);
    main_kernel<<<GRID_MAIN, THREADS, SM_TOTAL>>>(Wg, out);
}

// round 10
// speedup vs baseline: 2.6147x; 1.1194x over previous
#include <cuda_runtime.h>
#include <cuda_fp16.h>
#include <cstdint>

// ================= problem constants =================
#define NB   1024
#define IIC  128
#define MGLOB (NB*784)            // 802816 flattened output rows
#define MT    128                 // m per tile
#define NTILES (MGLOB/MT)         // 6272 exact
#define GRID_MAIN 304
#define THREADS 256

// ================= scratch =================
// g_R[(n*28+h')][idx 0..31][l 0..31]  fp16, 64B rows
__device__ __half g_R[(size_t)NB*28*32*32];   // 58.7 MB
__device__ int g_next;            // work-stealing counter
__device__ int g_done;            // reset coordinator

// ================= smem layout =================
#define WS_B32   (18*8*32*4)                    // 18432 b32 = 73728 B
#define WS_BYTES (WS_B32*4)
#define ACT_B32  2048                           // 8192 B per buffer
#define NBUF     4
#define SM_TOTAL (WS_BYTES + NBUF*ACT_B32*4)    // 106496

__device__ __forceinline__ void mma_f16(float4& d, const uint4& a, const uint2& b) {
    asm volatile(
        "mma.sync.aligned.m16n8k16.row.col.f32.f16.f16.f32 "
        "{%0,%1,%2,%3}, {%4,%5,%6,%7}, {%8,%9}, {%0,%1,%2,%3};"
        : "+f"(d.x), "+f"(d.y), "+f"(d.z), "+f"(d.w)
        : "r"(a.x), "r"(a.y), "r"(a.z), "r"(a.w), "r"(b.x), "r"(b.y));
}

// pair-local named barrier: warps {2p, 2p+1}, 64 threads, id p+1
#define PAIRBAR(p) asm volatile("bar.sync %0, 64;" :: "r"((p) + 1) : "memory")

// ================= prep kernel (unchanged, validated R9) =================
__global__ __launch_bounds__(128) void prep_kernel(const float* __restrict__ x) {
    __shared__ float xs[64 * 29];
    const int p = blockIdx.x;            // n*28 + h'
    const int n = p / 28, h = p - n * 28;
    const int tid = threadIdx.x;

    const float4* x4 = reinterpret_cast<const float4*>(x);
    #pragma unroll 4
    for (int e = tid; e < 448; e += 128) {
        const int c = e / 7, f = e - c * 7;
        const float4 v = x4[((size_t)(n * 64 + c) * 28 + h) * 7 + f];
        float* dst = &xs[c * 29 + f * 4];
        dst[0] = v.x; dst[1] = v.y; dst[2] = v.z; dst[3] = v.w;
    }
    __syncthreads();

    __half* Rout = g_R + (size_t)p * 1024;
    const int l = tid & 31;
    const int q0 = tid >> 5;
    #pragma unroll
    for (int qq = 0; qq < 8; ++qq) {
        const int q = qq * 4 + q0;
        float v;
        if (q < 28) {
            int u1 = q - 1; if (u1 < 0) u1 += 28;
            int u2 = q - 2; if (u2 < 0) u2 += 28;
            v = xs[l * 29 + u1] + xs[(32 + l) * 29 + u2];
        } else if (q == 28) v = xs[(32 + l) * 29 + 25];   // k=0, w=0
        else if (q == 29)   v = xs[l * 29 + 27];          // k=0, w=1
        else if (q == 30)   v = xs[l * 29 + 0];           // k=2, w=0
        else                v = xs[(32 + l) * 29 + 26];   // k=2, w=27
        Rout[q * 32 + l] = __float2half_rn(v);
    }
}

// ================= main kernel =================
__global__ __launch_bounds__(THREADS, 2) void main_kernel(const float* __restrict__ Wg,
                                                          float* __restrict__ out) {
    extern __shared__ char smem[];
    uint32_t* wsb = reinterpret_cast<uint32_t*>(smem);
    const uint4* ws4 = reinterpret_cast<const uint4*>(smem);
    uint32_t* act_base = reinterpret_cast<uint32_t*>(smem + WS_BYTES);

    const int tid  = threadIdx.x;
    const int lane = tid & 31;
    const int w    = tid >> 5;
    const int warp_i = w & 1;       // 64i half
    const int warp_m = w >> 1;      // pair id p: 32m octant
    const int gq  = lane >> 2;      // fragment groupID
    const int tig = lane & 3;       // thread-in-group

    // ---- weights -> fp16 fragment-ready smem, once per CTA (validated R9) ----
    for (int t = tid; t < WS_B32; t += THREADS) {
        const int reg = t & 3;
        const int ln  = (t >> 2) & 31;
        const int mt  = (t >> 7) & 7;
        const int S   = t >> 10;                  // 0..17
        const int r   = (ln >> 2) + ((reg & 1) << 3);
        const int k16 = ((ln & 3) << 1) + ((reg >> 1) << 3);
        const int i   = (mt << 4) + r;
        const int kp  = (S << 4) + k16;           // even
        const int c   = kp >> 5, l = kp & 31;
        const float w0 = Wg[(l * 9 + c) * 128 + i];
        const float w1 = Wg[((l + 1) * 9 + c) * 128 + i];
        const __half2 hv = __floats2half2_rn(w0, w1);
        wsb[t] = *reinterpret_cast<const uint32_t*>(&hv);
    }
    __syncthreads();   // only full-CTA barrier

    // rr-dependent swizzled lane offsets for B-frag loads
    int lofs[4];
    #pragma unroll
    for (int rr = 0; rr < 4; ++rr)
        lofs[rr] = ((gq ^ (rr << 1)) << 2) + tig;

    // ---- staging identity: 2 q-rows of 8, one 16B slot (8 l) each ----
    const int srow = lane >> 2;     // 0..7
    const int slot = lane & 3;      // rr
    int dstb[2];
    #pragma unroll
    for (int q = 0; q < 2; ++q) {
        const int m_loc = warp_m * 32 + warp_i * 16 + q * 8 + srow;
        dstb[q] = (((slot << 4) + (m_loc >> 3)) << 5)
                + (((m_loc & 7) ^ (slot << 1)) << 2);
    }

    // ---- dynamic tile loop ----
    while (true) {
        int g;
        if (tid == 0) g = atomicAdd(&g_next, 1);
        g = __shfl_sync(0xFFFFFFFFu, g, 0);
        g = __reduce_max_sync(0xFFFFFFFFu, g);   // broadcast within warp
        __shared__ int g_sh;
        if (tid == 0) g_sh = g;
        __syncthreads();
        g = g_sh;
        if (g >= NTILES) break;

        const int mbase = g * MT;

        // per-row metadata (registers)
        int hq[2], baseq[2], ikp[2];
        #pragma unroll
        for (int q = 0; q < 2; ++q) {
            const int m_loc = warp_m * 32 + warp_i * 16 + q * 8 + srow;
            const int mg = mbase + m_loc;
            const int n  = mg / 784;
            const int r  = mg - n * 784;
            const int h  = r / 28;
            const int wp = r - h * 28;
            hq[q]    = h;
            baseq[q] = (n * 28 + h) << 10;        // halves
            const int ik0 = (wp == 0) ? 28 : (wp == 1) ? 29 : (wp - 1);
            const int ik2 = (wp == 0) ? 30 : (wp == 27) ? 31 : (wp + 1);
            ikp[q] = ik0 | (wp << 5) | (ik2 << 10);
        }

        uint4 sv[2];
        // LDG helper inlined via lambda-like macro
        #define LDG_CHUNK(cn)  do {                                              \
            const int jj = ((cn) * 11) >> 5;                                     \
            const int kk = (cn) - jj * 3;                                        \
            _Pragma("unroll")                                                    \
            for (int q = 0; q < 2; ++q) {                                        \
                const int hp = hq[q] + jj - 1;                                   \
                const int ik = (ikp[q] >> (kk * 5)) & 31;                        \
                const int off = baseq[q] + ((jj - 1) << 10) + (ik << 5);         \
                sv[q] = make_uint4(0u, 0u, 0u, 0u);                              \
                if ((unsigned)hp < 28u)                                          \
                    sv[q] = *reinterpret_cast<const uint4*>(g_R + off + (slot << 3)); \
            } } while (0)
        #define STS_CHUNK(cn) do {                                               \
            uint32_t* bufn = act_base + ((cn) & 3) * ACT_B32;                    \
            _Pragma("unroll")                                                    \
            for (int q = 0; q < 2; ++q)                                          \
                *reinterpret_cast<uint4*>(bufn + dstb[q]) = sv[q];               \
            } while (0)

        // ---- prologue: stage chunks 0,1; LDG chunk 2 in flight ----
        LDG_CHUNK(0); STS_CHUNK(0);
        LDG_CHUNK(1); STS_CHUNK(1);
        LDG_CHUNK(2);
        PAIRBAR(warp_m);

        float4 acc[4][4];
        #pragma unroll
        for (int a = 0; a < 4; ++a)
            #pragma unroll
            for (int b = 0; b < 4; ++b)
                acc[a][b] = make_float4(0.f, 0.f, 0.f, 0.f);

        // ---- 9 chunks: STS(c+2) -> LDG(c+3) -> MMA(c) -> bar after odd c & 8 ----
        #pragma unroll 1
        for (int c = 0; c < 9; ++c) {
            if (c <= 6) STS_CHUNK(c + 2);
            if (c <= 5) LDG_CHUNK(c + 3);

            const uint32_t* bufc = act_base + (c & 3) * ACT_B32;
            #pragma unroll
            for (int s = 0; s < 2; ++s) {
                const int S = c * 2 + s;
                uint4 afr[4];
                #pragma unroll
                for (int mtl = 0; mtl < 4; ++mtl)
                    afr[mtl] = ws4[((S << 3) + warp_i * 4 + mtl) * 32 + lane];
                uint2 bfr[4];
                const int rr0 = s * 2, rr1 = s * 2 + 1;
                #pragma unroll
                for (int ntl = 0; ntl < 4; ++ntl) {
                    const int nt = warp_m * 4 + ntl;
                    bfr[ntl].x = bufc[(((rr0 << 4) + nt) << 5) + lofs[rr0]];
                    bfr[ntl].y = bufc[(((rr1 << 4) + nt) << 5) + lofs[rr1]];
                }
                #pragma unroll
                for (int mtl = 0; mtl < 4; ++mtl)
                    #pragma unroll
                    for (int ntl = 0; ntl < 4; ++ntl)
                        mma_f16(acc[mtl][ntl], afr[mtl], bfr[ntl]);
            }

            if ((c & 1) || c == 8) PAIRBAR(warp_m);
        }

        // ---- epilogue: coalesced float2 stores ----
        #pragma unroll
        for (int mtl = 0; mtl < 4; ++mtl) {
            const int i0 = warp_i * 64 + mtl * 16 + gq;
            #pragma unroll
            for (int ntl = 0; ntl < 4; ++ntl) {
                const int mgo = mbase + warp_m * 32 + ntl * 8 + (tig << 1);
                const int n = mgo / 784;
                const int r = mgo - n * 784;     // float2 never straddles n (mgo even)
                const float4 v = acc[mtl][ntl];
                float* ob = out + (size_t)n * (IIC * 784) + r;
                *reinterpret_cast<float2*>(ob + (size_t)i0 * 784)       = make_float2(v.x, v.y);
                *reinterpret_cast<float2*>(ob + (size_t)(i0 + 8) * 784) = make_float2(v.z, v.w);
            }
        }
        // next tile's prologue STS(0)->buf0 safe: MMA(8,buf0) of both warps done at c=8 bar
        #undef LDG_CHUNK
        #undef STS_CHUNK
    }

    // ---- self-reset of work counters (deterministic, graph-replay safe) ----
    __syncthreads();
    if (tid == 0) {
        const int old = atomicAdd(&g_done, 1);
        if (old == GRID_MAIN - 1) {   // every CTA has finished all its work
            g_next = 0;
            __threadfence();
            g_done = 0;
        }
    }
}

// ================= launch =================
extern "C" void kernel_launch(void* const* d_in, const int* in_sizes, int n_in,
                              void* d_out, int out_size) {
    const float* x  = (const float*)d_in[0];   // (1024,64,28,28)
    const float* Wg = (const float*)d_in[1];   // (32,3,3,128)
    float* out = (float*)d_out;                // (1024,128,28,28)

    prep_kernel<<<NB * 28, 128>>>(x);

    cudaFuncSetAttribute(main_kernel, cudaFuncAttributeMaxDynamicSharedMemorySize, SM_TOTAL);
    main_kernel<<<GRID_MAIN, THREADS, SM_TOTAL>>>(Wg, out);
}